// round 7
// baseline (speedup 1.0000x reference)
#include <cuda_runtime.h>
#include <cuda_bf16.h>
#include <math.h>

// B=8, D=64, T=512, O=256 (fixed by the reference)
#define PB 8
#define PD 64
#define PT 512
#define PO 256
#define THREADS 128
#define THALF 256          // t-points per block (T/2)

typedef unsigned long long u64;

// Partial sums workspace: [t-half][(b*D+d)*O+o] = {sw1, sy1, sw2, sy2}
__device__ float4 g_part[2][PB * PD * PO];
// One ticket per (b, d, o-half). Combining block resets it -> graph-replay safe.
__device__ unsigned g_tick[PB * PD * 2];

__device__ __forceinline__ float ex2a(float x) {
    float y; asm("ex2.approx.ftz.f32 %0, %1;" : "=f"(y) : "f"(x)); return y;
}
__device__ __forceinline__ float lg2a(float x) {
    float y; asm("lg2.approx.ftz.f32 %0, %1;" : "=f"(y) : "f"(x)); return y;
}
__device__ __forceinline__ u64 pk2(float lo, float hi) {
    u64 r; asm("mov.b64 %0, {%1, %2};" : "=l"(r) : "f"(lo), "f"(hi)); return r;
}
__device__ __forceinline__ void upk2(u64 v, float& lo, float& hi) {
    asm("mov.b64 {%0, %1}, %2;" : "=f"(lo), "=f"(hi) : "l"(v));
}
__device__ __forceinline__ u64 fma2(u64 a, u64 b, u64 c) {
    u64 d; asm("fma.rn.f32x2 %0, %1, %2, %3;" : "=l"(d) : "l"(a), "l"(b), "l"(c)); return d;
}
__device__ __forceinline__ u64 mul2(u64 a, u64 b) {
    u64 d; asm("mul.rn.f32x2 %0, %1, %2;" : "=l"(d) : "l"(a), "l"(b)); return d;
}
__device__ __forceinline__ u64 add2(u64 a, u64 b) {
    u64 d; asm("add.rn.f32x2 %0, %1, %2;" : "=l"(d) : "l"(a), "l"(b)); return d;
}

__global__ __launch_bounds__(THREADS, 8)
void interp_kernel(const float* __restrict__ x,
                   const float* __restrict__ grid,
                   const float* __restrict__ kern,
                   float* __restrict__ out) {
    // 2048 blocks: (b, d, o-half, t-half). 128 threads, one output column each,
    // summing over this block's 256 t-points. Last block per (b,d,oh) combines.
    const int bid = blockIdx.x;
    const int th  = bid & 1;                  // t-half
    const int oh  = (bid >> 1) & 1;           // o-half
    const int d   = (bid >> 2) & (PD - 1);
    const int b   = bid >> 8;
    const int tid  = threadIdx.x;
    const int lane = tid & 31;
    const int wid  = tid >> 5;                // 0..3, owns 64 t-points

    // AoS: {A=c1*t^2, B=-2*c1*t} interleaved -> LDS.128 loads a point-pair.
    __shared__ __align__(16) float2 sAB[THALF + 8];
    __shared__ __align__(16) float  sV[THALF + 8];
    __shared__ int swcnt[4];
    __shared__ int s_n;
    __shared__ int s_last;

    const size_t xoff = (size_t)(b * 3 * PD + d) * PT + th * THALF;
    const float* vp = x + xoff;
    const float* mp = x + xoff + (size_t)PD * PT;
    const float* tp = x + xoff + (size_t)(2 * PD) * PT;

    const float k = kern[d];
    const float alpha = (k > 20.0f) ? k : log1pf(__expf(k));
    const float c1 = -alpha * 1.4426950408889634f;   // -alpha*log2(e)

    // ---- Block-contiguous compaction (active points have m == 1 exactly) ----
    // Each warp owns local t in [64*wid, 64*wid+64): 2 ballot rounds.
    float tv0, vv0, tv1, vv1;
    unsigned bal0, bal1;
    int pos0, pos1, wcnt;
    {
        const int tbase = wid * 64;
        const int t0 = tbase + lane;
        const int t1 = tbase + 32 + lane;
        const float m0 = mp[t0];
        const float m1 = mp[t1];
        tv0 = tp[t0]; vv0 = vp[t0];
        tv1 = tp[t1]; vv1 = vp[t1];
        bal0 = __ballot_sync(0xffffffffu, m0 > 0.5f);
        bal1 = __ballot_sync(0xffffffffu, m1 > 0.5f);
        pos0 = __popc(bal0 & ((1u << lane) - 1u));
        pos1 = __popc(bal0) + __popc(bal1 & ((1u << lane) - 1u));
        wcnt = __popc(bal0) + __popc(bal1);
        if (lane == 0) swcnt[wid] = wcnt;
    }
    __syncthreads();
    int wbase = 0;
    #pragma unroll
    for (int w = 0; w < 4; w++)
        if (w < wid) wbase += swcnt[w];
    {
        if (bal0 & (1u << lane)) {
            const int i = wbase + pos0;
            sAB[i] = make_float2(c1 * tv0 * tv0, -2.0f * c1 * tv0);
            sV[i]  = vv0;
        }
        if (bal1 & (1u << lane)) {
            const int i = wbase + pos1;
            sAB[i] = make_float2(c1 * tv1 * tv1, -2.0f * c1 * tv1);
            sV[i]  = vv1;
        }
        if (tid == 0)
            s_n = swcnt[0] + swcnt[1] + swcnt[2] + swcnt[3];
    }
    __syncthreads();
    const int n = s_n;
    const int npad = (n + 7) & ~7;             // multiple of 8 points (4 pairs)
    for (int i = n + tid; i < npad; i += THREADS) {
        sAB[i] = make_float2(-160.0f, 0.0f);   // 2^-160 -> FTZ 0: zero weight
        sV[i]  = 0.0f;
    }
    __syncthreads();

    const int o = oh * 128 + tid;
    const float g = grid[b * PO + o];

    u64 aw1 = 0, ay1 = 0, aw2 = 0, ay2 = 0;

    const int npairs = npad >> 1;
    for (int i = 0; i < npairs; i += 4) {
        #pragma unroll
        for (int p = 0; p < 4; p++) {
            const int pr = i + p;
            const float4 ab = *(const float4*)(sAB + 2 * pr); // A0 B0 A1 B1
            const u64 Vp = *(const u64*)(sV + 2 * pr);
            const float a0 = __fmaf_rn(ab.y, g, ab.x);        // scalar args
            const float a1 = __fmaf_rn(ab.w, g, ab.z);
            const u64 E1 = pk2(ex2a(a0), ex2a(a1));
            const u64 s2 = mul2(E1, E1);
            const u64 s4 = mul2(s2, s2);
            const u64 s8 = mul2(s4, s4);
            const u64 E2 = mul2(s8, s2);                      // e1^10 (logm==0)
            aw1 = add2(aw1, E1);
            ay1 = fma2(E1, Vp, ay1);
            aw2 = add2(aw2, E2);
            ay2 = fma2(E2, Vp, ay2);
        }
    }

    float w1l, w1h, y1l, y1h, w2l, w2h, y2l, y2h;
    upk2(aw1, w1l, w1h); upk2(ay1, y1l, y1h);
    upk2(aw2, w2l, w2h); upk2(ay2, y2l, y2h);
    const float p_w1 = w1l + w1h;
    const float p_y1 = y1l + y1h;
    const float p_w2 = w2l + w2h;
    const float p_y2 = y2l + y2h;

    const int pi = (b * PD + d) * PO + o;
    g_part[th][pi] = make_float4(p_w1, p_y1, p_w2, p_y2);

    // ---- Last-block combine (ticket per (b,d,oh)) ----
    __threadfence();
    __syncthreads();
    if (tid == 0)
        s_last = (atomicAdd(&g_tick[bid >> 1], 1u) == 1u);
    __syncthreads();

    if (s_last) {
        const float4 peer = __ldcg(&g_part[1 - th][pi]);
        const float sw1 = p_w1 + peer.x;
        const float sy1 = p_y1 + peer.y;
        const float sw2 = p_w2 + peer.z;
        const float sy2 = p_y2 + peer.w;

        const float w = (lg2a(sw1) + c1 * g * g) * 0.6931471805599453f;

        float* ob = out + (size_t)(b * 3 * PD) * PO + o;
        ob[(size_t)(d) * PO]          = __fdividef(sy1, sw1);  // y
        ob[(size_t)(PD + d) * PO]     = w;                     // w (logsumexp)
        ob[(size_t)(2 * PD + d) * PO] = __fdividef(sy2, sw2);  // y_trans

        if (tid == 0) g_tick[bid >> 1] = 0u;   // reset for next graph replay
    }
}

extern "C" void kernel_launch(void* const* d_in, const int* in_sizes, int n_in,
                              void* d_out, int out_size) {
    const float* x    = (const float*)d_in[0];   // (8, 192, 512)
    const float* grid = (const float*)d_in[1];   // (8, 256)
    const float* kern = (const float*)d_in[2];   // (64,)
    float* out = (float*)d_out;                  // (8, 192, 256)

    interp_kernel<<<PB * PD * 4, THREADS>>>(x, grid, kern, out);
}

// round 8
// speedup vs baseline: 1.0815x; 1.0815x over previous
#include <cuda_runtime.h>
#include <cuda_bf16.h>
#include <math.h>

// B=8, D=64, T=512, O=256 (fixed by the reference)
#define PB 8
#define PD 64
#define PT 512
#define PO 256
#define THREADS 128
#define THALF 256          // t-points per block (T/2)

typedef unsigned long long u64;

// Partial sums workspace: [t-half][(b*D+d)*O+o] = {sw1, sy1, sw2, sy2}
__device__ float4 g_part[2][PB * PD * PO];
// One ticket per (b, d). Combining block resets it -> graph-replay safe.
__device__ unsigned g_tick[PB * PD];

__device__ __forceinline__ float ex2a(float x) {
    float y; asm("ex2.approx.ftz.f32 %0, %1;" : "=f"(y) : "f"(x)); return y;
}
__device__ __forceinline__ float lg2a(float x) {
    float y; asm("lg2.approx.ftz.f32 %0, %1;" : "=f"(y) : "f"(x)); return y;
}
__device__ __forceinline__ u64 pk2(float lo, float hi) {
    u64 r; asm("mov.b64 %0, {%1, %2};" : "=l"(r) : "f"(lo), "f"(hi)); return r;
}
__device__ __forceinline__ void upk2(u64 v, float& lo, float& hi) {
    asm("mov.b64 {%0, %1}, %2;" : "=f"(lo), "=f"(hi) : "l"(v));
}
__device__ __forceinline__ u64 fma2(u64 a, u64 b, u64 c) {
    u64 d; asm("fma.rn.f32x2 %0, %1, %2, %3;" : "=l"(d) : "l"(a), "l"(b), "l"(c)); return d;
}
__device__ __forceinline__ u64 add2(u64 a, u64 b) {
    u64 d; asm("add.rn.f32x2 %0, %1, %2;" : "=l"(d) : "l"(a), "l"(b)); return d;
}

__global__ __launch_bounds__(THREADS, 8)
void interp_kernel(const float* __restrict__ x,
                   const float* __restrict__ grid,
                   const float* __restrict__ kern,
                   float* __restrict__ out) {
    // 1024 blocks: (b, d, t-half). 128 threads; thread owns adjacent outputs
    // (2*tid, 2*tid+1), summing over this block's 256 t-points.
    const int bid = blockIdx.x;
    const int th  = bid & 1;                  // t-half
    const int d   = (bid >> 1) & (PD - 1);
    const int b   = bid >> 7;
    const int tid  = threadIdx.x;
    const int lane = tid & 31;
    const int wid  = tid >> 5;                // 0..3, owns 64 t-points

    // Per-t data: {A=c1*t^2, B=-2*c1*t, rho=2^(B*h), rho^10}; V separate.
    __shared__ __align__(16) float4 sAB[THALF + 4];
    __shared__ __align__(16) float  sV[THALF + 4];
    __shared__ int swcnt[4];
    __shared__ int s_n;
    __shared__ int s_last;

    const size_t xoff = (size_t)(b * 3 * PD + d) * PT + th * THALF;
    const float* vp = x + xoff;
    const float* mp = x + xoff + (size_t)PD * PT;
    const float* tp = x + xoff + (size_t)(2 * PD) * PT;

    const float k = kern[d];
    const float alpha = (k > 20.0f) ? k : log1pf(__expf(k));
    const float c1 = -alpha * 1.4426950408889634f;   // -alpha*log2(e)
    const float h  = 1.0f / 255.0f;                  // grid spacing

    // ---- Block-contiguous compaction (active points have m == 1 exactly) ----
    {
        const int tbase = wid * 64;
        const int t0 = tbase + lane;
        const int t1 = tbase + 32 + lane;
        const float m0 = mp[t0];
        const float m1 = mp[t1];
        const float tv0 = tp[t0], vv0 = vp[t0];
        const float tv1 = tp[t1], vv1 = vp[t1];
        const unsigned bal0 = __ballot_sync(0xffffffffu, m0 > 0.5f);
        const unsigned bal1 = __ballot_sync(0xffffffffu, m1 > 0.5f);
        const int pos0 = __popc(bal0 & ((1u << lane) - 1u));
        const int pos1 = __popc(bal0) + __popc(bal1 & ((1u << lane) - 1u));
        if (lane == 0) swcnt[wid] = __popc(bal0) + __popc(bal1);
        __syncthreads();
        int wbase = 0;
        #pragma unroll
        for (int w = 0; w < 4; w++)
            if (w < wid) wbase += swcnt[w];
        if (bal0 & (1u << lane)) {
            const int i = wbase + pos0;
            const float Bc = -2.0f * c1 * tv0;
            const float r  = ex2a(Bc * h);
            sAB[i] = make_float4(c1 * tv0 * tv0, Bc, r, ex2a(10.0f * Bc * h));
            sV[i]  = vv0;
        }
        if (bal1 & (1u << lane)) {
            const int i = wbase + pos1;
            const float Bc = -2.0f * c1 * tv1;
            const float r  = ex2a(Bc * h);
            sAB[i] = make_float4(c1 * tv1 * tv1, Bc, r, ex2a(10.0f * Bc * h));
            sV[i]  = vv1;
        }
        if (tid == 0)
            s_n = swcnt[0] + swcnt[1] + swcnt[2] + swcnt[3];
    }
    __syncthreads();
    const int n = s_n;
    const int npad = (n + 3) & ~3;
    for (int i = n + tid; i < npad; i += THREADS) {
        sAB[i] = make_float4(-160.0f, 0.0f, 0.0f, 0.0f);  // zero weight
        sV[i]  = 0.0f;
    }
    __syncthreads();

    const int o0 = 2 * tid;
    const int o1 = o0 + 1;
    const float g0 = grid[b * PO + o0];
    const float g1 = grid[b * PO + o1];

    u64 aw1 = 0, ay1 = 0, aw2 = 0, ay2 = 0;   // lanes = (o0, o1)

    for (int i = 0; i < npad; i += 4) {
        #pragma unroll
        for (int p = 0; p < 4; p++) {
            const float4 e = sAB[i + p];             // A, B, rho, rho10
            const float  v = sV[i + p];
            const float arg = __fmaf_rn(e.y, g0, e.x);
            const float E0  = ex2a(arg);             // the only EX2 (2 outputs)
            const float E1  = E0 * e.z;              // ratio step to o1
            const float c2  = E0 * E0;
            const float c4  = c2 * c2;
            const float c8  = c4 * c4;
            const float T0  = c8 * c2;               // E0^10 (logm == 0)
            const float T1  = T0 * e.w;              // E1^10
            const u64 Ep = pk2(E0, E1);
            const u64 Tp = pk2(T0, T1);
            const u64 Vp = pk2(v, v);
            aw1 = add2(aw1, Ep);
            ay1 = fma2(Ep, Vp, ay1);
            aw2 = add2(aw2, Tp);
            ay2 = fma2(Tp, Vp, ay2);
        }
    }

    // Unpack per-o partials (lane lo = o0, hi = o1).
    float w1a, w1b, y1a, y1b, w2a, w2b, y2a, y2b;
    upk2(aw1, w1a, w1b); upk2(ay1, y1a, y1b);
    upk2(aw2, w2a, w2b); upk2(ay2, y2a, y2b);

    const int pib = (b * PD + d) * PO;
    g_part[th][pib + o0] = make_float4(w1a, y1a, w2a, y2a);
    g_part[th][pib + o1] = make_float4(w1b, y1b, w2b, y2b);

    // ---- Last-block combine (ticket per (b,d)) ----
    __threadfence();
    __syncthreads();
    if (tid == 0)
        s_last = (atomicAdd(&g_tick[bid >> 1], 1u) == 1u);
    __syncthreads();

    if (s_last) {
        const float4 pe0 = __ldcg(&g_part[1 - th][pib + o0]);
        const float4 pe1 = __ldcg(&g_part[1 - th][pib + o1]);
        const float sw1a = w1a + pe0.x, sy1a = y1a + pe0.y;
        const float sw2a = w2a + pe0.z, sy2a = y2a + pe0.w;
        const float sw1b = w1b + pe1.x, sy1b = y1b + pe1.y;
        const float sw2b = w2b + pe1.z, sy2b = y2b + pe1.w;

        const float ln2 = 0.6931471805599453f;
        const float wa = (lg2a(sw1a) + c1 * g0 * g0) * ln2;
        const float wb = (lg2a(sw1b) + c1 * g1 * g1) * ln2;

        float* ob = out + (size_t)(b * 3 * PD) * PO;
        ob[(size_t)(d) * PO + o0]          = __fdividef(sy1a, sw1a);
        ob[(size_t)(d) * PO + o1]          = __fdividef(sy1b, sw1b);
        ob[(size_t)(PD + d) * PO + o0]     = wa;
        ob[(size_t)(PD + d) * PO + o1]     = wb;
        ob[(size_t)(2 * PD + d) * PO + o0] = __fdividef(sy2a, sw2a);
        ob[(size_t)(2 * PD + d) * PO + o1] = __fdividef(sy2b, sw2b);

        if (tid == 0) g_tick[bid >> 1] = 0u;   // reset for next graph replay
    }
}

extern "C" void kernel_launch(void* const* d_in, const int* in_sizes, int n_in,
                              void* d_out, int out_size) {
    const float* x    = (const float*)d_in[0];   // (8, 192, 512)
    const float* grid = (const float*)d_in[1];   // (8, 256)
    const float* kern = (const float*)d_in[2];   // (64,)
    float* out = (float*)d_out;                  // (8, 192, 256)

    interp_kernel<<<PB * PD * 2, THREADS>>>(x, grid, kern, out);
}